// round 2
// baseline (speedup 1.0000x reference)
#include <cuda_runtime.h>
#include <math.h>

#define N_TOK  8192
#define DMODEL 1024
#define HDIM   4096
#define NEXP   8
#define CAP    8192   // max rows per expert bucket (token picks each expert at most once)

// ---------------- device scratch (static; no allocations) ----------------
__device__ int   g_counts[NEXP];
__device__ int   g_bucket[NEXP * CAP];          // entry = 2*token + slot
__device__ float g_g0[N_TOK], g_g1[N_TOK], g_xn[N_TOK];
__device__ float g_h[(size_t)2 * N_TOK * HDIM];     // 256 MB, indexed by pair id
__device__ float g_y[(size_t)2 * N_TOK * DMODEL];   // 64 MB,  indexed by pair id

// ---------------- kernel 0: reset bucket counts ----------------
__global__ void zero_counts_kernel() {
    if (threadIdx.x < NEXP) g_counts[threadIdx.x] = 0;
}

// ---------------- kernel 1: gating (logits, top-2, softmax, ||x||, bucket) ----------------
__global__ void gate_kernel(const float* __restrict__ x, const float* __restrict__ wg) {
    int t = blockIdx.x, tid = threadIdx.x;
    float acc[NEXP];
#pragma unroll
    for (int e = 0; e < NEXP; e++) acc[e] = 0.f;
    float sq = 0.f;
    const float* xr = x + (size_t)t * DMODEL;
    for (int d = tid; d < DMODEL; d += 256) {
        float xv = xr[d];
        sq += xv * xv;
        const float* w = wg + (size_t)d * NEXP;
#pragma unroll
        for (int e = 0; e < NEXP; e++) acc[e] += xv * w[e];
    }
#pragma unroll
    for (int off = 16; off > 0; off >>= 1) {
#pragma unroll
        for (int e = 0; e < NEXP; e++) acc[e] += __shfl_down_sync(0xffffffffu, acc[e], off);
        sq += __shfl_down_sync(0xffffffffu, sq, off);
    }
    __shared__ float wacc[8][NEXP];
    __shared__ float wsq[8];
    int warp = tid >> 5, lane = tid & 31;
    if (lane == 0) {
#pragma unroll
        for (int e = 0; e < NEXP; e++) wacc[warp][e] = acc[e];
        wsq[warp] = sq;
    }
    __syncthreads();
    if (tid == 0) {
        float lg[NEXP];
        float s = 0.f;
#pragma unroll
        for (int e = 0; e < NEXP; e++) {
            float v = 0.f;
            for (int w = 0; w < 8; w++) v += wacc[w][e];
            lg[e] = v;
        }
        for (int w = 0; w < 8; w++) s += wsq[w];
        // top-2 (first occurrence wins ties, matching jax.lax.top_k)
        int i0 = 0;
        for (int e = 1; e < NEXP; e++) if (lg[e] > lg[i0]) i0 = e;
        int i1 = -1;
        for (int e = 0; e < NEXP; e++) {
            if (e == i0) continue;
            if (i1 < 0 || lg[e] > lg[i1]) i1 = e;
        }
        float v0 = lg[i0], v1 = lg[i1];
        float e1 = expf(v1 - v0);           // v0 >= v1, numerically stable
        float g1v = e1 / (1.f + e1);
        float g0v = 1.f - g1v;
        g_g0[t] = g0v;
        g_g1[t] = g1v;
        g_xn[t] = sqrtf(s);
        int p0 = atomicAdd(&g_counts[i0], 1);
        g_bucket[i0 * CAP + p0] = 2 * t;
        int p1 = atomicAdd(&g_counts[i1], 1);
        g_bucket[i1 * CAP + p1] = 2 * t + 1;
    }
}

// ---------------- kernels 2/3: grouped fp32 GEMM, 128x128x8 tiles, 8x8 per thread ----------------
// WHICH==0: h = relu(gather(x) @ w1[e] + b1[e])   (K=1024, N=4096, A row = ent>>1, C = g_h)
// WHICH==1: y = g_h @ w2[e] + b2[e]               (K=4096, N=1024, A row = ent,    C = g_y)
template <int WHICH>
__global__ __launch_bounds__(256, 2) void grouped_gemm_kernel(
    const float* __restrict__ X, const float* __restrict__ W, const float* __restrict__ bias) {
    constexpr int  KDIM   = (WHICH == 0) ? DMODEL : HDIM;
    constexpr int  NDIM   = (WHICH == 0) ? HDIM : DMODEL;
    constexpr int  ASHIFT = (WHICH == 0) ? 1 : 0;
    constexpr bool RELU   = (WHICH == 0);
    const float* A_src = (WHICH == 0) ? X : (const float*)g_h;
    float*       C     = (WHICH == 0) ? g_h : g_y;

    int e   = blockIdx.z;
    int cnt = g_counts[e];
    int m0  = blockIdx.y * 128;
    if (m0 >= cnt) return;
    int n0  = blockIdx.x * 128;

    __shared__ float As[8][128];
    __shared__ float Bs[8][128];
    __shared__ int   ents[128];

    int tid = threadIdx.x;
    for (int i = tid; i < 128; i += 256) {
        int r = m0 + i;
        ents[i] = (r < cnt) ? g_bucket[e * CAP + r] : g_bucket[e * CAP];  // clamp to valid
    }
    __syncthreads();

    int a_row = tid >> 1;
    int a_col = (tid & 1) * 4;
    const float* a_ptr = A_src + (size_t)(ents[a_row] >> ASHIFT) * KDIM + a_col;
    int b_row = tid >> 5;
    int b_col = (tid & 31) * 4;
    const float* w_ptr = W + (size_t)e * KDIM * NDIM + (size_t)b_row * NDIM + n0 + b_col;

    int ty = tid >> 4, tx = tid & 15;
    float accv[8][8];
#pragma unroll
    for (int i = 0; i < 8; i++)
#pragma unroll
        for (int j = 0; j < 8; j++) accv[i][j] = 0.f;

    float4 av = *(const float4*)(a_ptr);
    float4 bv = *(const float4*)(w_ptr);

    for (int k0 = 0; k0 < KDIM; k0 += 8) {
        As[a_col + 0][a_row] = av.x;
        As[a_col + 1][a_row] = av.y;
        As[a_col + 2][a_row] = av.z;
        As[a_col + 3][a_row] = av.w;
        *(float4*)&Bs[b_row][b_col] = bv;
        __syncthreads();
        if (k0 + 8 < KDIM) {  // prefetch next tile while computing
            av = *(const float4*)(a_ptr + k0 + 8);
            bv = *(const float4*)(w_ptr + (size_t)(k0 + 8) * NDIM);
        }
#pragma unroll
        for (int kk = 0; kk < 8; kk++) {
            float a[8], b[8];
#pragma unroll
            for (int i = 0; i < 8; i++) a[i] = As[kk][ty * 8 + i];
#pragma unroll
            for (int j = 0; j < 8; j++) b[j] = Bs[kk][tx * 8 + j];
#pragma unroll
            for (int i = 0; i < 8; i++)
#pragma unroll
                for (int j = 0; j < 8; j++) accv[i][j] += a[i] * b[j];
        }
        __syncthreads();
    }

    const float* bb = bias + (size_t)e * NDIM + n0 + tx * 8;
    float bvals[8];
#pragma unroll
    for (int j = 0; j < 8; j++) bvals[j] = bb[j];
#pragma unroll
    for (int i = 0; i < 8; i++) {
        int r = m0 + ty * 8 + i;
        if (r >= cnt) continue;
        int ent = ents[ty * 8 + i];
        float* dst = C + (size_t)ent * NDIM + n0 + tx * 8;
#pragma unroll
        for (int j = 0; j < 8; j++) {
            float v = accv[i][j] + bvals[j];
            if (RELU) v = fmaxf(v, 0.f);
            dst[j] = v;
        }
    }
}

// ---------------- kernel 4: per-token norm-rescale + gated combine ----------------
__global__ void combine_kernel(float* __restrict__ out) {
    int t = blockIdx.x, tid = threadIdx.x;
    const float* y0 = g_y + (size_t)(2 * t) * DMODEL;
    const float* y1 = y0 + DMODEL;
    float r0[4], r1[4];
    float p0 = 0.f, p1 = 0.f;
#pragma unroll
    for (int it = 0; it < 4; it++) {
        int d = tid + it * 256;
        float a = y0[d]; r0[it] = a; p0 += a * a;
        float b = y1[d]; r1[it] = b; p1 += b * b;
    }
#pragma unroll
    for (int off = 16; off > 0; off >>= 1) {
        p0 += __shfl_down_sync(0xffffffffu, p0, off);
        p1 += __shfl_down_sync(0xffffffffu, p1, off);
    }
    __shared__ float w0[8], w1s[8], sc[2];
    int warp = tid >> 5, lane = tid & 31;
    if (lane == 0) { w0[warp] = p0; w1s[warp] = p1; }
    __syncthreads();
    if (tid == 0) {
        float n0 = 0.f, n1 = 0.f;
        for (int w = 0; w < 8; w++) { n0 += w0[w]; n1 += w1s[w]; }
        float xn = g_xn[t];
        sc[0] = g_g0[t] * xn / (sqrtf(n0) + 1e-8f);
        sc[1] = g_g1[t] * xn / (sqrtf(n1) + 1e-8f);
    }
    __syncthreads();
    float s0 = sc[0], s1 = sc[1];
#pragma unroll
    for (int it = 0; it < 4; it++) {
        int d = tid + it * 256;
        out[(size_t)t * DMODEL + d] = s0 * r0[it] + s1 * r1[it];
    }
}

// ---------------- launch ----------------
extern "C" void kernel_launch(void* const* d_in, const int* in_sizes, int n_in,
                              void* d_out, int out_size) {
    const float* x  = (const float*)d_in[0];
    const float* wg = (const float*)d_in[1];
    const float* w1 = (const float*)d_in[2];
    const float* b1 = (const float*)d_in[3];
    const float* w2 = (const float*)d_in[4];
    const float* b2 = (const float*)d_in[5];
    float* out = (float*)d_out;

    zero_counts_kernel<<<1, 32>>>();
    gate_kernel<<<N_TOK, 256>>>(x, wg);

    dim3 grid1(HDIM / 128, CAP / 128, NEXP);   // 32 x 64 x 8
    grouped_gemm_kernel<0><<<grid1, 256>>>(x, w1, b1);

    dim3 grid2(DMODEL / 128, CAP / 128, NEXP); // 8 x 64 x 8
    grouped_gemm_kernel<1><<<grid2, 256>>>(nullptr, w2, b2);

    combine_kernel<<<N_TOK, 256>>>(out);
}

// round 3
// speedup vs baseline: 2.8135x; 2.8135x over previous
#include <cuda_runtime.h>
#include <math.h>
#include <stdint.h>

#define N_TOK  8192
#define DMODEL 1024
#define HDIM   4096
#define NEXP   8
#define CAP    8192

// ---------------- device scratch (static; no allocations) ----------------
__device__ int   g_counts[NEXP];
__device__ int   g_bucket[NEXP * CAP];          // entry = 2*token + slot
__device__ float g_g0[N_TOK], g_g1[N_TOK], g_xn[N_TOK];
__device__ float g_h[(size_t)2 * N_TOK * HDIM];     // 256 MB, indexed by pair id
__device__ float g_y[(size_t)2 * N_TOK * DMODEL];   // 64 MB,  indexed by pair id

// ---------------- helpers ----------------
__device__ __forceinline__ uint32_t smem_u32(const void* p) {
    return (uint32_t)__cvta_generic_to_shared(p);
}
__device__ __forceinline__ void cp_async16(uint32_t dst, const void* src) {
    asm volatile("cp.async.cg.shared.global [%0], [%1], 16;\n" :: "r"(dst), "l"(src));
}
__device__ __forceinline__ void cp_commit() { asm volatile("cp.async.commit_group;\n"); }
template <int N>
__device__ __forceinline__ void cp_wait() { asm volatile("cp.async.wait_group %0;\n" :: "n"(N)); }
__device__ __forceinline__ uint32_t f2tf32(float f) {
    uint32_t r;
    asm("cvt.rna.tf32.f32 %0, %1;\n" : "=r"(r) : "f"(f));
    return r;
}
__device__ __forceinline__ void mma_tf32(float* d, const uint32_t* a, const uint32_t* b) {
    asm volatile(
        "mma.sync.aligned.m16n8k8.row.col.f32.tf32.tf32.f32 "
        "{%0,%1,%2,%3}, {%4,%5,%6,%7}, {%8,%9}, {%0,%1,%2,%3};\n"
        : "+f"(d[0]), "+f"(d[1]), "+f"(d[2]), "+f"(d[3])
        : "r"(a[0]), "r"(a[1]), "r"(a[2]), "r"(a[3]), "r"(b[0]), "r"(b[1]));
}

// ---------------- kernel 0: reset bucket counts ----------------
__global__ void zero_counts_kernel() {
    if (threadIdx.x < NEXP) g_counts[threadIdx.x] = 0;
}

// ---------------- kernel 1: gating ----------------
__global__ void gate_kernel(const float* __restrict__ x, const float* __restrict__ wg) {
    int t = blockIdx.x, tid = threadIdx.x;
    float acc[NEXP];
#pragma unroll
    for (int e = 0; e < NEXP; e++) acc[e] = 0.f;
    float sq = 0.f;
    const float* xr = x + (size_t)t * DMODEL;
    for (int d = tid; d < DMODEL; d += 256) {
        float xv = xr[d];
        sq += xv * xv;
        const float* w = wg + (size_t)d * NEXP;
#pragma unroll
        for (int e = 0; e < NEXP; e++) acc[e] += xv * w[e];
    }
#pragma unroll
    for (int off = 16; off > 0; off >>= 1) {
#pragma unroll
        for (int e = 0; e < NEXP; e++) acc[e] += __shfl_down_sync(0xffffffffu, acc[e], off);
        sq += __shfl_down_sync(0xffffffffu, sq, off);
    }
    __shared__ float wacc[8][NEXP];
    __shared__ float wsq[8];
    int warp = tid >> 5, lane = tid & 31;
    if (lane == 0) {
#pragma unroll
        for (int e = 0; e < NEXP; e++) wacc[warp][e] = acc[e];
        wsq[warp] = sq;
    }
    __syncthreads();
    if (tid == 0) {
        float lg[NEXP];
        float s = 0.f;
#pragma unroll
        for (int e = 0; e < NEXP; e++) {
            float v = 0.f;
            for (int w = 0; w < 8; w++) v += wacc[w][e];
            lg[e] = v;
        }
        for (int w = 0; w < 8; w++) s += wsq[w];
        int i0 = 0;
        for (int e = 1; e < NEXP; e++) if (lg[e] > lg[i0]) i0 = e;
        int i1 = -1;
        for (int e = 0; e < NEXP; e++) {
            if (e == i0) continue;
            if (i1 < 0 || lg[e] > lg[i1]) i1 = e;
        }
        float v0 = lg[i0], v1 = lg[i1];
        float e1 = expf(v1 - v0);
        float g1v = e1 / (1.f + e1);
        g_g0[t] = 1.f - g1v;
        g_g1[t] = g1v;
        g_xn[t] = sqrtf(s);
        int p0 = atomicAdd(&g_counts[i0], 1);
        g_bucket[i0 * CAP + p0] = 2 * t;
        int p1 = atomicAdd(&g_counts[i1], 1);
        g_bucket[i1 * CAP + p1] = 2 * t + 1;
    }
}

// ---------------- tf32 tensor-core grouped GEMM ----------------
// Tiles: 128(M) x 128(N) x 32(K). 256 threads = 8 warps in 4(M) x 2(N).
// Each warp: 32x64 via 2x8 m16n8k8 fragments.
// WHICH==0: h = relu(gather(x) @ w1[e] + b1[e])   K=1024, N=4096, Arow = ent>>1, C = g_h
// WHICH==1: y = g_h @ w2[e] + b2[e]               K=4096, N=1024, Arow = ent,    C = g_y
#define AS_STRIDE 36      // 128 rows x 36 (32 k + pad): bank = (4m + k) % 32, conflict-free frags
#define BS_STRIDE 136     // 32 rows  x 136 (128 n + pad): bank = (8k + n) % 32, conflict-free frags
#define AS_FLOATS (128 * AS_STRIDE)   // 4608
#define BS_FLOATS (32 * BS_STRIDE)    // 4352
#define SMEM_FLOATS (2 * AS_FLOATS + 2 * BS_FLOATS)  // 17920
#define GEMM_SMEM_BYTES (SMEM_FLOATS * 4 + 128 * 4)  // + ents

template <int WHICH>
__global__ __launch_bounds__(256) void mma_gemm_kernel(
    const float* __restrict__ X, const float* __restrict__ W, const float* __restrict__ bias) {
    constexpr int  KDIM   = (WHICH == 0) ? DMODEL : HDIM;
    constexpr int  NDIM   = (WHICH == 0) ? HDIM : DMODEL;
    constexpr int  ASHIFT = (WHICH == 0) ? 1 : 0;
    constexpr bool RELU   = (WHICH == 0);
    constexpr int  KTILES = KDIM / 32;
    const float* A_src = (WHICH == 0) ? X : (const float*)g_h;
    float*       C     = (WHICH == 0) ? g_h : g_y;

    int e   = blockIdx.z;
    int cnt = g_counts[e];
    int m0  = blockIdx.y * 128;
    if (m0 >= cnt) return;
    int n0  = blockIdx.x * 128;

    extern __shared__ float smem[];
    float* As[2] = {smem, smem + AS_FLOATS};
    float* Bs[2] = {smem + 2 * AS_FLOATS, smem + 2 * AS_FLOATS + BS_FLOATS};
    int*   ents  = (int*)(smem + SMEM_FLOATS);

    int tid = threadIdx.x;
    for (int i = tid; i < 128; i += 256) {
        int r = m0 + i;
        ents[i] = (r < cnt) ? g_bucket[e * CAP + r] : g_bucket[e * CAP];
    }
    __syncthreads();

    // ---- per-thread load assignments (4 x 16B for A, 4 x 16B for B per tile) ----
    int rowA  = tid >> 3;            // + i*32
    int ksubA = (tid & 7) * 4;
    const float* aPtr[4];
    uint32_t     aDst[4];
#pragma unroll
    for (int i = 0; i < 4; i++) {
        int r = rowA + i * 32;
        aPtr[i] = A_src + (size_t)(ents[r] >> ASHIFT) * KDIM + ksubA;
        aDst[i] = smem_u32(&As[0][r * AS_STRIDE + ksubA]);
    }
    int rowB  = tid >> 5;            // + i*8
    int nsubB = (tid & 31) * 4;
    const float* bPtr[4];
    uint32_t     bDst[4];
    const float* Wbase = W + (size_t)e * KDIM * NDIM + n0;
#pragma unroll
    for (int i = 0; i < 4; i++) {
        int r = rowB + i * 8;
        bPtr[i] = Wbase + (size_t)r * NDIM + nsubB;
        bDst[i] = smem_u32(&Bs[0][r * BS_STRIDE + nsubB]);
    }
    const uint32_t aBufOff = AS_FLOATS * 4;   // bytes between A buffers
    const uint32_t bBufOff = BS_FLOATS * 4;

    // ---- fragment coordinates ----
    int warp = tid >> 5, lane = tid & 31;
    int warp_m = (warp >> 1) * 32;
    int warp_n = (warp & 1) * 64;
    int l4 = lane >> 2, lk = lane & 3;

    float acc[2][8][4];
#pragma unroll
    for (int im = 0; im < 2; im++)
#pragma unroll
        for (int jn = 0; jn < 8; jn++)
#pragma unroll
            for (int c = 0; c < 4; c++) acc[im][jn][c] = 0.f;

    // ---- prologue: load tile 0 ----
#pragma unroll
    for (int i = 0; i < 4; i++) cp_async16(aDst[i], aPtr[i]);
#pragma unroll
    for (int i = 0; i < 4; i++) cp_async16(bDst[i], bPtr[i]);
    cp_commit();

    for (int kt = 0; kt < KTILES; kt++) {
        int cur = kt & 1;
        if (kt + 1 < KTILES) {
            int nxt = 1 - cur;
            int k0n = (kt + 1) * 32;
#pragma unroll
            for (int i = 0; i < 4; i++) cp_async16(aDst[i] + nxt * aBufOff, aPtr[i] + k0n);
#pragma unroll
            for (int i = 0; i < 4; i++) cp_async16(bDst[i] + nxt * bBufOff, bPtr[i] + (size_t)k0n * NDIM);
            cp_commit();
            cp_wait<1>();
        } else {
            cp_wait<0>();
        }
        __syncthreads();

        const float* Ab = As[cur];
        const float* Bb = Bs[cur];
#pragma unroll
        for (int ks = 0; ks < 4; ks++) {
            int kk = ks * 8;
            uint32_t af[2][4];
#pragma unroll
            for (int im = 0; im < 2; im++) {
                int m = warp_m + im * 16 + l4;
                af[im][0] = f2tf32(Ab[(m) * AS_STRIDE + kk + lk]);
                af[im][1] = f2tf32(Ab[(m + 8) * AS_STRIDE + kk + lk]);
                af[im][2] = f2tf32(Ab[(m) * AS_STRIDE + kk + lk + 4]);
                af[im][3] = f2tf32(Ab[(m + 8) * AS_STRIDE + kk + lk + 4]);
            }
            uint32_t bf[8][2];
#pragma unroll
            for (int jn = 0; jn < 8; jn++) {
                int nn = warp_n + jn * 8 + l4;
                bf[jn][0] = f2tf32(Bb[(kk + lk) * BS_STRIDE + nn]);
                bf[jn][1] = f2tf32(Bb[(kk + lk + 4) * BS_STRIDE + nn]);
            }
#pragma unroll
            for (int im = 0; im < 2; im++)
#pragma unroll
                for (int jn = 0; jn < 8; jn++)
                    mma_tf32(acc[im][jn], af[im], bf[jn]);
        }
        __syncthreads();
    }

    // ---- epilogue: bias (+relu) and scatter by bucket entry ----
#pragma unroll
    for (int im = 0; im < 2; im++) {
#pragma unroll
        for (int h = 0; h < 2; h++) {     // h=0: c0/c1 (row), h=1: c2/c3 (row+8)
            int row = warp_m + im * 16 + l4 + h * 8;
            int r = m0 + row;
            if (r >= cnt) continue;
            int ent = ents[row];
            float* dst = C + (size_t)ent * NDIM + n0;
            const float* bb = bias + (size_t)e * NDIM + n0;
#pragma unroll
            for (int jn = 0; jn < 8; jn++) {
                int col = warp_n + jn * 8 + 2 * lk;
                float v0 = acc[im][jn][2 * h + 0] + bb[col];
                float v1 = acc[im][jn][2 * h + 1] + bb[col + 1];
                if (RELU) { v0 = fmaxf(v0, 0.f); v1 = fmaxf(v1, 0.f); }
                *(float2*)(dst + col) = make_float2(v0, v1);
            }
        }
    }
}

// ---------------- kernel 4: per-token norm-rescale + gated combine ----------------
__global__ void combine_kernel(float* __restrict__ out) {
    int t = blockIdx.x, tid = threadIdx.x;
    const float* y0 = g_y + (size_t)(2 * t) * DMODEL;
    const float* y1 = y0 + DMODEL;
    float r0[4], r1[4];
    float p0 = 0.f, p1 = 0.f;
#pragma unroll
    for (int it = 0; it < 4; it++) {
        int d = tid + it * 256;
        float a = y0[d]; r0[it] = a; p0 += a * a;
        float b = y1[d]; r1[it] = b; p1 += b * b;
    }
#pragma unroll
    for (int off = 16; off > 0; off >>= 1) {
        p0 += __shfl_down_sync(0xffffffffu, p0, off);
        p1 += __shfl_down_sync(0xffffffffu, p1, off);
    }
    __shared__ float w0[8], w1s[8], sc[2];
    int warp = tid >> 5, lane = tid & 31;
    if (lane == 0) { w0[warp] = p0; w1s[warp] = p1; }
    __syncthreads();
    if (tid == 0) {
        float n0 = 0.f, n1 = 0.f;
        for (int w = 0; w < 8; w++) { n0 += w0[w]; n1 += w1s[w]; }
        float xn = g_xn[t];
        sc[0] = g_g0[t] * xn / (sqrtf(n0) + 1e-8f);
        sc[1] = g_g1[t] * xn / (sqrtf(n1) + 1e-8f);
    }
    __syncthreads();
    float s0 = sc[0], s1 = sc[1];
#pragma unroll
    for (int it = 0; it < 4; it++) {
        int d = tid + it * 256;
        out[(size_t)t * DMODEL + d] = s0 * r0[it] + s1 * r1[it];
    }
}

// ---------------- launch ----------------
extern "C" void kernel_launch(void* const* d_in, const int* in_sizes, int n_in,
                              void* d_out, int out_size) {
    const float* x  = (const float*)d_in[0];
    const float* wg = (const float*)d_in[1];
    const float* w1 = (const float*)d_in[2];
    const float* b1 = (const float*)d_in[3];
    const float* w2 = (const float*)d_in[4];
    const float* b2 = (const float*)d_in[5];
    float* out = (float*)d_out;

    static bool attr_done = false;
    if (!attr_done) {
        cudaFuncSetAttribute(mma_gemm_kernel<0>,
                             cudaFuncAttributeMaxDynamicSharedMemorySize, GEMM_SMEM_BYTES);
        cudaFuncSetAttribute(mma_gemm_kernel<1>,
                             cudaFuncAttributeMaxDynamicSharedMemorySize, GEMM_SMEM_BYTES);
        attr_done = true;
    }

    zero_counts_kernel<<<1, 32>>>();
    gate_kernel<<<N_TOK, 256>>>(x, wg);

    dim3 grid1(HDIM / 128, CAP / 128, NEXP);   // 32 x 64 x 8
    mma_gemm_kernel<0><<<grid1, 256, GEMM_SMEM_BYTES>>>(x, w1, b1);

    dim3 grid2(DMODEL / 128, CAP / 128, NEXP); // 8 x 64 x 8
    mma_gemm_kernel<1><<<grid2, 256, GEMM_SMEM_BYTES>>>(nullptr, w2, b2);

    combine_kernel<<<N_TOK, 256>>>(out);
}